// round 10
// baseline (speedup 1.0000x reference)
#include <cuda_runtime.h>

#define BB 2
#define NN 131072
#define KK 20
#define EE 256
#define TEMP_INV 20.0f
#define SCORE_THRESH 0.04f

typedef unsigned long long u64;

// ---- packed f32x2 helpers (FFMA2 is PTX-only on sm_103a) ----
__device__ __forceinline__ u64 fma2(u64 a, u64 b, u64 c) {
    u64 d; asm("fma.rn.f32x2 %0, %1, %2, %3;" : "=l"(d) : "l"(a), "l"(b), "l"(c));
    return d;
}
__device__ __forceinline__ u64 pk(float a, float b) {
    u64 r; asm("mov.b64 %0, {%1, %2};" : "=l"(r) : "f"(a), "f"(b)); return r;
}
__device__ __forceinline__ float f2sum(u64 v) {
    float lo, hi; asm("mov.b64 {%0, %1}, %2;" : "=f"(lo), "=f"(hi) : "l"(v));
    return lo + hi;
}
__device__ __forceinline__ void unpk(u64 v, float& lo, float& hi) {
    asm("mov.b64 {%0, %1}, %2;" : "=f"(lo), "=f"(hi) : "l"(v));
}

// ---- scratch ----
__device__ float g_x[BB * KK * EE];
__device__ u64   g_snpack[BB * EE * 10];        // [b][e][j]: (sn[2j][e], sn[2j+1][e])
__device__ float g_scores[BB * KK];
__device__ float g_mask[(size_t)BB * KK * NN];  // [b][k][n]

// sn in the constant bank -> LDCU (uniform port), zero l1tex traffic.
__constant__ ulonglong2 c_sn2[BB][EE][5];       // 40 KB

// ============================================================
// k1a: x[b][k][o] = sum_e slots[b][k][e] * w1[o][e] + b1[o]  (40 blocks)
// ============================================================
__global__ void k1a(const float* __restrict__ slots, const float* __restrict__ w1,
                    const float* __restrict__ b1) {
    int g = blockIdx.x * 256 + threadIdx.x;
    if (g < BB * KK) g_scores[g] = 0.f;
    int b = g / (KK * EE);
    int rem = g % (KK * EE);
    int k = rem / EE;
    int o = rem % EE;
    const float4* sr = (const float4*)(slots + (size_t)(b * KK + k) * EE);
    const float4* wr = (const float4*)(w1 + (size_t)o * EE);
    u64 acc = 0;
#pragma unroll 8
    for (int i = 0; i < EE / 4; i++) {
        float4 s = __ldg(&sr[i]);
        float4 w = __ldg(&wr[i]);
        acc = fma2(pk(w.x, w.y), pk(s.x, s.y), acc);
        acc = fma2(pk(w.z, w.w), pk(s.z, s.w), acc);
    }
    g_x[(b * KK + k) * EE + o] = f2sum(acc) + __ldg(&b1[o]);
}

// ============================================================
// k1b: GroupNorm (64 ch x 20 slots) per (b, group) + affine + ReLU
// ============================================================
__global__ void k1b(const float* __restrict__ gn_g, const float* __restrict__ gn_b) {
    int b = blockIdx.x >> 2, grp = blockIdx.x & 3;
    int t = threadIdx.x;
    float s = 0.f, ss = 0.f;
    for (int i = t; i < KK * 64; i += 256) {
        int k = i >> 6, oo = (i & 63) + grp * 64;
        float v = g_x[(b * KK + k) * EE + oo];
        s += v; ss += v * v;
    }
    __shared__ float rs[8], rss[8];
    for (int off = 16; off; off >>= 1) {
        s  += __shfl_xor_sync(0xffffffffu, s, off);
        ss += __shfl_xor_sync(0xffffffffu, ss, off);
    }
    if ((t & 31) == 0) { rs[t >> 5] = s; rss[t >> 5] = ss; }
    __syncthreads();
    if (t == 0) {
        float a = 0.f, q = 0.f;
        for (int i = 0; i < 8; i++) { a += rs[i]; q += rss[i]; }
        rs[0] = a; rss[0] = q;
    }
    __syncthreads();
    float mu  = rs[0] * (1.f / 1280.f);
    float var = rss[0] * (1.f / 1280.f) - mu * mu;
    float sc  = rsqrtf(var + 1e-5f);
    for (int i = t; i < KK * 64; i += 256) {
        int k = i >> 6, oo = (i & 63) + grp * 64;
        int idx = (b * KK + k) * EE + oo;
        float v = (g_x[idx] - mu) * sc * __ldg(&gn_g[oo]) + __ldg(&gn_b[oo]);
        g_x[idx] = fmaxf(v, 0.f);
    }
}

// ============================================================
// k1c: slot = W2 @ x + b2, l2norm, *1/TEMP, direct packed write. Block per (b,k).
// ============================================================
__global__ void __launch_bounds__(256) k1c(const float* __restrict__ w2,
                                           const float* __restrict__ b2) {
    int b = blockIdx.x / KK, k = blockIdx.x % KK;
    int f = threadIdx.x;
    __shared__ float sx[EE];
    sx[f] = g_x[(b * KK + k) * EE + f];
    __syncthreads();
    const float4* wr = (const float4*)(w2 + (size_t)f * EE);
    const float4* xr = (const float4*)sx;
    u64 acc = 0;
#pragma unroll 8
    for (int i = 0; i < EE / 4; i++) {
        float4 w = __ldg(&wr[i]);
        float4 x = xr[i];
        acc = fma2(pk(w.x, w.y), pk(x.x, x.y), acc);
        acc = fma2(pk(w.z, w.w), pk(x.z, x.w), acc);
    }
    float d = f2sum(acc) + __ldg(&b2[f]);
    float q = d * d;
    __shared__ float rq[8];
    for (int off = 16; off; off >>= 1) q += __shfl_xor_sync(0xffffffffu, q, off);
    if ((f & 31) == 0) rq[f >> 5] = q;
    __syncthreads();
    __shared__ float rinv_s;
    if (f == 0) {
        float a = 0.f;
        for (int i = 0; i < 8; i++) a += rq[i];
        rinv_s = rsqrtf(fmaxf(a, 1e-24f)) * TEMP_INV;
    }
    __syncthreads();
    float* sp = (float*)g_snpack;
    sp[((size_t)(b * EE + f) * 10 + (k >> 1)) * 2 + (k & 1)] = d * rinv_s;
}

// ============================================================
// k2: GEMV-batch + softmax, R=2 rows/thread, sn via LDCU (imm offsets).
// 64-THREAD blocks: same 24 warps/SM in wave 1, but the scheduling quantum is
// 128 rows, so the final wave's tail runs at low contention instead of
// costing a full extra 50us wave. Two template kernels forked concurrently.
// ============================================================
template <int B_>
__global__ void __launch_bounds__(64, 12) k2(const float* __restrict__ features) {
    __shared__ float s_sc[KK];
    int t = threadIdx.x;
    if (t < KK) s_sc[t] = 0.f;
    __syncthreads();
    int n0 = blockIdx.x * 128 + t;
    int n1 = n0 + 64;

    const float4* fv0 = (const float4*)(features + ((size_t)B_ * NN + n0) * EE);
    const float4* fv1 = (const float4*)(features + ((size_t)B_ * NN + n1) * EE);

    u64 acc0[10], acc1[10];
#pragma unroll
    for (int j = 0; j < 10; j++) { acc0[j] = 0; acc1[j] = 0; }
    u64 na0 = 0, na1 = 0;

#pragma unroll 4
    for (int e4 = 0; e4 < 64; e4++) {
        float4 f0 = __ldg(&fv0[e4]);
        float4 f1 = __ldg(&fv1[e4]);
        u64 p0a = pk(f0.x, f0.y), p0b = pk(f0.z, f0.w);
        u64 p1a = pk(f1.x, f1.y), p1b = pk(f1.z, f1.w);
        na0 = fma2(p0a, p0a, na0); na0 = fma2(p0b, p0b, na0);
        na1 = fma2(p1a, p1a, na1); na1 = fma2(p1b, p1b, na1);
        float fe0[4] = {f0.x, f0.y, f0.z, f0.w};
        float fe1[4] = {f1.x, f1.y, f1.z, f1.w};
#pragma unroll
        for (int e = 0; e < 4; e++) {
            u64 sp0 = pk(fe0[e], fe0[e]);
            u64 sp1 = pk(fe1[e], fe1[e]);
#pragma unroll
            for (int m = 0; m < 5; m++) {
                ulonglong2 sv = c_sn2[B_][e4 * 4 + e][m];   // LDCU, imm offset
                acc0[2 * m]     = fma2(sp0, sv.x, acc0[2 * m]);
                acc0[2 * m + 1] = fma2(sp0, sv.y, acc0[2 * m + 1]);
                acc1[2 * m]     = fma2(sp1, sv.x, acc1[2 * m]);
                acc1[2 * m + 1] = fma2(sp1, sv.y, acc1[2 * m + 1]);
            }
        }
    }

    float d0[KK], d1[KK];
#pragma unroll
    for (int j = 0; j < 10; j++) {
        unpk(acc0[j], d0[2 * j], d0[2 * j + 1]);
        unpk(acc1[j], d1[2 * j], d1[2 * j + 1]);
    }
    float r0 = rsqrtf(fmaxf(f2sum(na0), 1e-24f));
    float r1 = rsqrtf(fmaxf(f2sum(na1), 1e-24f));
    float m0 = -1e30f, m1 = -1e30f;
#pragma unroll
    for (int k = 0; k < KK; k++) {
        d0[k] *= r0; d1[k] *= r1;
        m0 = fmaxf(m0, d0[k]); m1 = fmaxf(m1, d1[k]);
    }
    float s0 = 0.f, s1 = 0.f;
#pragma unroll
    for (int k = 0; k < KK; k++) {
        d0[k] = __expf(d0[k] - m0); s0 += d0[k];
        d1[k] = __expf(d1[k] - m1); s1 += d1[k];
    }
    float is0 = 1.f / s0, is1 = 1.f / s1;

#pragma unroll
    for (int k = 0; k < KK; k++) {
        float p0 = d0[k] * is0;
        float p1 = d1[k] * is1;
        size_t base = ((size_t)(B_ * KK + k)) * NN;
        g_mask[base + n0] = p0;
        g_mask[base + n1] = p1;
        float ws = p0 + p1;
        for (int off = 16; off; off >>= 1) ws += __shfl_xor_sync(0xffffffffu, ws, off);
        if ((t & 31) == 0) atomicAdd(&s_sc[k], ws);
    }
    __syncthreads();
    if (t < KK) atomicAdd(&g_scores[B_ * KK + t], s_sc[t]);
}

// ============================================================
// k4: fused NMS-logic + normalize + scatter.
// kept-sum trick: softmax rows sum to 1, so denom = 1 - sum(dropped planes).
// Pass over dropped planes (usually 0-2) + one streaming pass over kept ones:
// each mask plane is read exactly once.
// ============================================================
__global__ void __launch_bounds__(256) k4(float* __restrict__ out) {
    __shared__ int src[KK];        // kept source ks, score-desc order
    __shared__ int drop[KK];       // dropped ks
    __shared__ int nkeep_s;
    int t = threadIdx.x;
    const int bpb = NN / 512;
    int b  = blockIdx.x / bpb;
    int n2 = (blockIdx.x % bpb) * 256 + t;

    if (t == 0) {
        float sc[KK]; bool used[KK];
#pragma unroll
        for (int k = 0; k < KK; k++) {
            sc[k] = g_scores[b * KK + k] * (1.f / (float)NN);
            used[k] = false;
        }
        int pos = 0, dn = 0;
        for (int r = 0; r < KK; r++) {
            int best = 0; float bs = -1e30f;
            for (int k = 0; k < KK; k++)
                if (!used[k] && sc[k] > bs) { bs = sc[k]; best = k; }
            used[best] = true;
            if (bs >= SCORE_THRESH) src[pos++] = best;
            else                    drop[dn++] = best;
        }
        nkeep_s = pos;
    }
    __syncthreads();
    int nkeep = nkeep_s;

    const float2* mk = (const float2*)g_mask;
    float2* ov = (float2*)out;

    // denom = 1 - sum(dropped) (+1e-8)
    float2 s = make_float2(0.f, 0.f);
    for (int p = 0; p < KK - nkeep; p++) {
        float2 v = __ldg(&mk[((size_t)(b * KK + drop[p]) * NN) / 2 + n2]);
        s.x += v.x; s.y += v.y;
    }
    float2 is = make_float2(1.f / (1.f - s.x + 1e-8f), 1.f / (1.f - s.y + 1e-8f));

    for (int p = 0; p < nkeep; p++) {
        float2 v = __ldg(&mk[((size_t)(b * KK + src[p]) * NN) / 2 + n2]);
        v.x *= is.x; v.y *= is.y;
        ov[((size_t)(b * KK + p) * NN) / 2 + n2] = v;
    }
    float2 z = make_float2(0.f, 0.f);
    for (int p = nkeep; p < KK; p++)
        ov[((size_t)(b * KK + p) * NN) / 2 + n2] = z;
}

// ============================================================
extern "C" void kernel_launch(void* const* d_in, const int* in_sizes, int n_in,
                              void* d_out, int out_size) {
    const float* features = (const float*)d_in[0];
    const float* slots    = (const float*)d_in[1];
    const float* w1       = (const float*)d_in[2];
    const float* b1       = (const float*)d_in[3];
    const float* gn_g     = (const float*)d_in[4];
    const float* gn_b     = (const float*)d_in[5];
    const float* w2       = (const float*)d_in[6];
    const float* b2       = (const float*)d_in[7];

    k1a<<<(BB * KK * EE) / 256, 256>>>(slots, w1, b1);
    k1b<<<BB * 4, 256>>>(gn_g, gn_b);
    k1c<<<BB * KK, 256>>>(w2, b2);

    void* src = nullptr;
    cudaGetSymbolAddress(&src, g_snpack);
    cudaMemcpyToSymbolAsync(c_sn2, src, sizeof(u64) * BB * EE * 10, 0,
                            cudaMemcpyDeviceToDevice, 0);

    // Fork: run the two k2 template kernels concurrently.
    cudaStream_t s2;
    cudaStreamCreateWithFlags(&s2, cudaStreamNonBlocking);
    cudaEvent_t ef, ej;
    cudaEventCreateWithFlags(&ef, cudaEventDisableTiming);
    cudaEventCreateWithFlags(&ej, cudaEventDisableTiming);

    cudaEventRecord(ef, 0);
    cudaStreamWaitEvent(s2, ef, 0);
    k2<1><<<NN / 128, 64, 0, s2>>>(features);
    cudaEventRecord(ej, s2);

    k2<0><<<NN / 128, 64>>>(features);
    cudaStreamWaitEvent(0, ej, 0);

    k4<<<(BB * NN) / 512, 256>>>((float*)d_out);

    cudaEventDestroy(ef);
    cudaEventDestroy(ej);
    cudaStreamDestroy(s2);
}

// round 11
// speedup vs baseline: 1.1897x; 1.1897x over previous
#include <cuda_runtime.h>

#define BB 2
#define NN 131072
#define KK 20
#define EE 256
#define TEMP_INV 20.0f
#define SCORE_THRESH 0.04f

typedef unsigned long long u64;

// ---- packed f32x2 helpers (FFMA2 is PTX-only on sm_103a) ----
__device__ __forceinline__ u64 fma2(u64 a, u64 b, u64 c) {
    u64 d; asm("fma.rn.f32x2 %0, %1, %2, %3;" : "=l"(d) : "l"(a), "l"(b), "l"(c));
    return d;
}
__device__ __forceinline__ u64 pk(float a, float b) {
    u64 r; asm("mov.b64 %0, {%1, %2};" : "=l"(r) : "f"(a), "f"(b)); return r;
}
__device__ __forceinline__ float f2sum(u64 v) {
    float lo, hi; asm("mov.b64 {%0, %1}, %2;" : "=f"(lo), "=f"(hi) : "l"(v));
    return lo + hi;
}
__device__ __forceinline__ void unpk(u64 v, float& lo, float& hi) {
    asm("mov.b64 {%0, %1}, %2;" : "=f"(lo), "=f"(hi) : "l"(v));
}

// ---- scratch ----
__device__ float g_x[BB * KK * EE];
__device__ u64   g_snpack[BB * EE * 10];        // [b][e][j]: (sn[2j][e], sn[2j+1][e])
__device__ float g_scores[BB * KK];
__device__ float g_mask[(size_t)BB * KK * NN];  // [b][k][n]

// sn in the constant bank -> LDCU (uniform port), zero l1tex traffic.
__constant__ ulonglong2 c_sn2[BB][EE][5];       // 40 KB

// ============================================================
// k1a: x[b][k][o] = sum_e slots[b][k][e] * w1[o][e] + b1[o]  (40 blocks)
// ============================================================
__global__ void k1a(const float* __restrict__ slots, const float* __restrict__ w1,
                    const float* __restrict__ b1) {
    int g = blockIdx.x * 256 + threadIdx.x;
    if (g < BB * KK) g_scores[g] = 0.f;
    int b = g / (KK * EE);
    int rem = g % (KK * EE);
    int k = rem / EE;
    int o = rem % EE;
    const float4* sr = (const float4*)(slots + (size_t)(b * KK + k) * EE);
    const float4* wr = (const float4*)(w1 + (size_t)o * EE);
    u64 acc = 0;
#pragma unroll 8
    for (int i = 0; i < EE / 4; i++) {
        float4 s = __ldg(&sr[i]);
        float4 w = __ldg(&wr[i]);
        acc = fma2(pk(w.x, w.y), pk(s.x, s.y), acc);
        acc = fma2(pk(w.z, w.w), pk(s.z, s.w), acc);
    }
    g_x[(b * KK + k) * EE + o] = f2sum(acc) + __ldg(&b1[o]);
}

// ============================================================
// k1b: GroupNorm (64 ch x 20 slots) per (b, group) + affine + ReLU
// ============================================================
__global__ void k1b(const float* __restrict__ gn_g, const float* __restrict__ gn_b) {
    int b = blockIdx.x >> 2, grp = blockIdx.x & 3;
    int t = threadIdx.x;
    float s = 0.f, ss = 0.f;
    for (int i = t; i < KK * 64; i += 256) {
        int k = i >> 6, oo = (i & 63) + grp * 64;
        float v = g_x[(b * KK + k) * EE + oo];
        s += v; ss += v * v;
    }
    __shared__ float rs[8], rss[8];
    for (int off = 16; off; off >>= 1) {
        s  += __shfl_xor_sync(0xffffffffu, s, off);
        ss += __shfl_xor_sync(0xffffffffu, ss, off);
    }
    if ((t & 31) == 0) { rs[t >> 5] = s; rss[t >> 5] = ss; }
    __syncthreads();
    if (t == 0) {
        float a = 0.f, q = 0.f;
        for (int i = 0; i < 8; i++) { a += rs[i]; q += rss[i]; }
        rs[0] = a; rss[0] = q;
    }
    __syncthreads();
    float mu  = rs[0] * (1.f / 1280.f);
    float var = rss[0] * (1.f / 1280.f) - mu * mu;
    float sc  = rsqrtf(var + 1e-5f);
    for (int i = t; i < KK * 64; i += 256) {
        int k = i >> 6, oo = (i & 63) + grp * 64;
        int idx = (b * KK + k) * EE + oo;
        float v = (g_x[idx] - mu) * sc * __ldg(&gn_g[oo]) + __ldg(&gn_b[oo]);
        g_x[idx] = fmaxf(v, 0.f);
    }
}

// ============================================================
// k1c: slot = W2 @ x + b2, l2norm, *1/TEMP, direct packed write. Block per (b,k).
// ============================================================
__global__ void __launch_bounds__(256) k1c(const float* __restrict__ w2,
                                           const float* __restrict__ b2) {
    int b = blockIdx.x / KK, k = blockIdx.x % KK;
    int f = threadIdx.x;
    __shared__ float sx[EE];
    sx[f] = g_x[(b * KK + k) * EE + f];
    __syncthreads();
    const float4* wr = (const float4*)(w2 + (size_t)f * EE);
    const float4* xr = (const float4*)sx;
    u64 acc = 0;
#pragma unroll 8
    for (int i = 0; i < EE / 4; i++) {
        float4 w = __ldg(&wr[i]);
        float4 x = xr[i];
        acc = fma2(pk(w.x, w.y), pk(x.x, x.y), acc);
        acc = fma2(pk(w.z, w.w), pk(x.z, x.w), acc);
    }
    float d = f2sum(acc) + __ldg(&b2[f]);
    float q = d * d;
    __shared__ float rq[8];
    for (int off = 16; off; off >>= 1) q += __shfl_xor_sync(0xffffffffu, q, off);
    if ((f & 31) == 0) rq[f >> 5] = q;
    __syncthreads();
    __shared__ float rinv_s;
    if (f == 0) {
        float a = 0.f;
        for (int i = 0; i < 8; i++) a += rq[i];
        rinv_s = rsqrtf(fmaxf(a, 1e-24f)) * TEMP_INV;
    }
    __syncthreads();
    float* sp = (float*)g_snpack;
    sp[((size_t)(b * EE + f) * 10 + (k >> 1)) * 2 + (k & 1)] = d * rinv_s;
}

// ============================================================
// k2: GEMV-batch + softmax, R=2 rows/thread, sn via LDCU (imm offsets).
// __launch_bounds__(256, 4): target <=64 regs -> 4 blocks/SM (32 warps/SM),
// and 512 combined blocks fit the 592 slots in a SINGLE wave.
// unroll 2 halves the load-buffer register pressure (4 LDG.128 in flight).
// Two template kernels forked concurrently on separate streams.
// ============================================================
template <int B_>
__global__ void __launch_bounds__(256, 4) k2(const float* __restrict__ features) {
    __shared__ float s_sc[KK];
    int t = threadIdx.x;
    if (t < KK) s_sc[t] = 0.f;
    __syncthreads();
    int n0 = blockIdx.x * 512 + t;
    int n1 = n0 + 256;

    const float4* fv0 = (const float4*)(features + ((size_t)B_ * NN + n0) * EE);
    const float4* fv1 = (const float4*)(features + ((size_t)B_ * NN + n1) * EE);

    u64 acc0[10], acc1[10];
#pragma unroll
    for (int j = 0; j < 10; j++) { acc0[j] = 0; acc1[j] = 0; }
    u64 na0 = 0, na1 = 0;

#pragma unroll 2
    for (int e4 = 0; e4 < 64; e4++) {
        float4 f0 = __ldg(&fv0[e4]);
        float4 f1 = __ldg(&fv1[e4]);
        u64 p0a = pk(f0.x, f0.y), p0b = pk(f0.z, f0.w);
        u64 p1a = pk(f1.x, f1.y), p1b = pk(f1.z, f1.w);
        na0 = fma2(p0a, p0a, na0); na0 = fma2(p0b, p0b, na0);
        na1 = fma2(p1a, p1a, na1); na1 = fma2(p1b, p1b, na1);
        float fe0[4] = {f0.x, f0.y, f0.z, f0.w};
        float fe1[4] = {f1.x, f1.y, f1.z, f1.w};
#pragma unroll
        for (int e = 0; e < 4; e++) {
            u64 sp0 = pk(fe0[e], fe0[e]);
            u64 sp1 = pk(fe1[e], fe1[e]);
#pragma unroll
            for (int m = 0; m < 5; m++) {
                ulonglong2 sv = c_sn2[B_][e4 * 4 + e][m];   // LDCU, imm offset
                acc0[2 * m]     = fma2(sp0, sv.x, acc0[2 * m]);
                acc0[2 * m + 1] = fma2(sp0, sv.y, acc0[2 * m + 1]);
                acc1[2 * m]     = fma2(sp1, sv.x, acc1[2 * m]);
                acc1[2 * m + 1] = fma2(sp1, sv.y, acc1[2 * m + 1]);
            }
        }
    }

    float d0[KK], d1[KK];
#pragma unroll
    for (int j = 0; j < 10; j++) {
        unpk(acc0[j], d0[2 * j], d0[2 * j + 1]);
        unpk(acc1[j], d1[2 * j], d1[2 * j + 1]);
    }
    float r0 = rsqrtf(fmaxf(f2sum(na0), 1e-24f));
    float r1 = rsqrtf(fmaxf(f2sum(na1), 1e-24f));
    float m0 = -1e30f, m1 = -1e30f;
#pragma unroll
    for (int k = 0; k < KK; k++) {
        d0[k] *= r0; d1[k] *= r1;
        m0 = fmaxf(m0, d0[k]); m1 = fmaxf(m1, d1[k]);
    }
    float s0 = 0.f, s1 = 0.f;
#pragma unroll
    for (int k = 0; k < KK; k++) {
        d0[k] = __expf(d0[k] - m0); s0 += d0[k];
        d1[k] = __expf(d1[k] - m1); s1 += d1[k];
    }
    float is0 = 1.f / s0, is1 = 1.f / s1;

#pragma unroll
    for (int k = 0; k < KK; k++) {
        float p0 = d0[k] * is0;
        float p1 = d1[k] * is1;
        size_t base = ((size_t)(B_ * KK + k)) * NN;
        g_mask[base + n0] = p0;
        g_mask[base + n1] = p1;
        float ws = p0 + p1;
        for (int off = 16; off; off >>= 1) ws += __shfl_xor_sync(0xffffffffu, ws, off);
        if ((t & 31) == 0) atomicAdd(&s_sc[k], ws);
    }
    __syncthreads();
    if (t < KK) atomicAdd(&g_scores[B_ * KK + t], s_sc[t]);
}

// ============================================================
// k4: fused NMS-logic + normalize + scatter, float2/thread, two-pass.
// Softmax rows sum to 1 => binary masks disjoint => IoU off-diag 0 =>
// suppression never fires; kept = valid cols in stable desc-score order.
// ============================================================
__global__ void __launch_bounds__(256) k4(float* __restrict__ out) {
    __shared__ int src[KK];
    __shared__ int nkeep_s;
    int t = threadIdx.x;
    const int bpb = NN / 512;
    int b  = blockIdx.x / bpb;
    int n2 = (blockIdx.x % bpb) * 256 + t;

    if (t == 0) {
        float sc[KK]; bool used[KK];
#pragma unroll
        for (int k = 0; k < KK; k++) {
            sc[k] = g_scores[b * KK + k] * (1.f / (float)NN);
            used[k] = false;
        }
        int pos = 0;
        for (int r = 0; r < KK; r++) {
            int best = 0; float bs = -1e30f;
            for (int k = 0; k < KK; k++)
                if (!used[k] && sc[k] > bs) { bs = sc[k]; best = k; }
            used[best] = true;
            if (bs >= SCORE_THRESH) src[pos++] = best;
        }
        nkeep_s = pos;
        for (; pos < KK; pos++) src[pos] = -1;
    }
    __syncthreads();
    int nkeep = nkeep_s;

    const float2* mk = (const float2*)g_mask;
    float2* ov = (float2*)out;

    float2 s = make_float2(0.f, 0.f);
    for (int p = 0; p < nkeep; p++) {
        float2 v = __ldg(&mk[((size_t)(b * KK + src[p]) * NN) / 2 + n2]);
        s.x += v.x; s.y += v.y;
    }
    float2 is = make_float2(1.f / (s.x + 1e-8f), 1.f / (s.y + 1e-8f));

    for (int p = 0; p < nkeep; p++) {
        float2 v = __ldg(&mk[((size_t)(b * KK + src[p]) * NN) / 2 + n2]);
        v.x *= is.x; v.y *= is.y;
        ov[((size_t)(b * KK + p) * NN) / 2 + n2] = v;
    }
    float2 z = make_float2(0.f, 0.f);
    for (int p = nkeep; p < KK; p++)
        ov[((size_t)(b * KK + p) * NN) / 2 + n2] = z;
}

// ============================================================
extern "C" void kernel_launch(void* const* d_in, const int* in_sizes, int n_in,
                              void* d_out, int out_size) {
    const float* features = (const float*)d_in[0];
    const float* slots    = (const float*)d_in[1];
    const float* w1       = (const float*)d_in[2];
    const float* b1       = (const float*)d_in[3];
    const float* gn_g     = (const float*)d_in[4];
    const float* gn_b     = (const float*)d_in[5];
    const float* w2       = (const float*)d_in[6];
    const float* b2       = (const float*)d_in[7];

    k1a<<<(BB * KK * EE) / 256, 256>>>(slots, w1, b1);
    k1b<<<BB * 4, 256>>>(gn_g, gn_b);
    k1c<<<BB * KK, 256>>>(w2, b2);

    void* src = nullptr;
    cudaGetSymbolAddress(&src, g_snpack);
    cudaMemcpyToSymbolAsync(c_sn2, src, sizeof(u64) * BB * EE * 10, 0,
                            cudaMemcpyDeviceToDevice, 0);

    // Fork: run the two k2 template kernels concurrently.
    cudaStream_t s2;
    cudaStreamCreateWithFlags(&s2, cudaStreamNonBlocking);
    cudaEvent_t ef, ej;
    cudaEventCreateWithFlags(&ef, cudaEventDisableTiming);
    cudaEventCreateWithFlags(&ej, cudaEventDisableTiming);

    cudaEventRecord(ef, 0);
    cudaStreamWaitEvent(s2, ef, 0);
    k2<1><<<NN / 512, 256, 0, s2>>>(features);
    cudaEventRecord(ej, s2);

    k2<0><<<NN / 512, 256>>>(features);
    cudaStreamWaitEvent(0, ej, 0);

    k4<<<(BB * NN) / 512, 256>>>((float*)d_out);

    cudaEventDestroy(ef);
    cudaEventDestroy(ej);
    cudaStreamDestroy(s2);
}